// round 14
// baseline (speedup 1.0000x reference)
#include <cuda_runtime.h>
#include <cuda_bf16.h>
#include <cstdint>

#define N_NODES 100000
#define N_EDGES 1600000
#define D_IN 128
#define D_HID 128
#define D_LAT 64

// tcgen05 is arch-SPECIFIC (sm_103a / sm_100a). The harness also compiles a
// base-family compute_103 target, which rejects tcgen05 — so every tcgen05 use
// is gated on the arch-specific feature macros, with a SIMT fallback body.
#if !defined(__CUDA_ARCH__)
#define TC_OK 1   /* host pass: declarations only, nothing codegen'd */
#elif defined(__CUDA_ARCH_FEAT_SM103_ALL) || defined(__CUDA_ARCH_FEAT_SM100_ALL) || \
      (defined(__CUDA_ARCH_SPECIFIC__) && (__CUDA_ARCH_SPECIFIC__ >= 1000))
#define TC_OK 1
#else
#define TC_OK 0
#endif

// ---------------- scratch (static device globals; no allocation) ----------------
__device__ int   g_is64;
__device__ int   g_deg[N_NODES];
__device__ int   g_off[N_NODES + 1];
__device__ int   g_cursor[N_NODES];
__device__ int   g_bsums[128];
__device__ int   g_csr[N_EDGES];
__device__ float g_mean1[(size_t)N_NODES * 128];          // mean-aggregated x (fp32)
__device__ float g_h[(size_t)N_NODES * 128];              // R = x@W1r, then layer-1 output
__device__ __nv_bfloat16 g_t2l[(size_t)N_NODES * 64];     // h@W2_l (bf16, gather source)
__device__ float g_t2r[(size_t)N_NODES * 64];             // h@W2_r (fp32, self path)

// packed weight tiles: exact SW128-swizzled SMEM byte image, [hi|lo] bf16
__device__ __nv_bfloat16 g_Bp1[2][2][16384];   // [0]=W1l, [1]=W1r; [hi/lo]
__device__ __nv_bfloat16 g_Bp2[2][16384];      // [hi/lo] concat(W2l|W2r)

// ---------------- host-side fork/join infra (created once at load) ----------------
namespace {
struct GraphForkInfra {
    cudaStream_t s1 = nullptr;
    cudaEvent_t evFork = nullptr, evJoin = nullptr;
    GraphForkInfra() {
        cudaStreamCreateWithFlags(&s1, cudaStreamNonBlocking);
        cudaEventCreateWithFlags(&evFork, cudaEventDisableTiming);
        cudaEventCreateWithFlags(&evJoin, cudaEventDisableTiming);
    }
};
GraphForkInfra g_infra;
}

// ---------------- small PTX helpers (arch-portable) ----------------
__device__ __forceinline__ uint32_t smem_u32(const void* p) {
    uint32_t a;
    asm("{ .reg .u64 t; cvta.to.shared.u64 t, %1; cvt.u32.u64 %0, t; }" : "=r"(a) : "l"(p));
    return a;
}
__device__ __forceinline__ uint32_t elect_one() {
    uint32_t pred;
    asm volatile("{\n\t.reg .pred p;\n\telect.sync _|p, 0xFFFFFFFF;\n\tselp.b32 %0, 1, 0, p;\n\t}"
                 : "=r"(pred));
    return pred;
}

#define MBARRIER_INIT(addr, cnt) \
    asm volatile("mbarrier.init.shared.b64 [%0], %1;" :: "r"(addr), "r"(cnt) : "memory")

#define MBARRIER_WAIT_PARITY(addr, par) do {                                            \
    uint32_t _m = (addr), _p = (par), _d;                                               \
    asm volatile("{\n\t.reg .pred p;\n\t"                                               \
        "mbarrier.try_wait.parity.acquire.cta.shared::cta.b64 p, [%1], %2;\n\t"          \
        "selp.b32 %0, 1, 0, p;\n\t}" : "=r"(_d) : "r"(_m), "r"(_p) : "memory");          \
    if (!_d) {                                                                           \
        asm volatile("{\n\t.reg .pred P1;\n\t"                                           \
            "WL_%=:\n\t"                                                                 \
            "mbarrier.try_wait.parity.acquire.cta.shared::cta.b64 P1, [%0], %1, 0x989680;\n\t" \
            "@P1 bra.uni WD_%=;\n\t"                                                     \
            "bra.uni WL_%=;\n\t"                                                         \
            "WD_%=:\n\t}" :: "r"(_m), "r"(_p) : "memory");                               \
    }                                                                                    \
} while (0)

// ---------------- f32x2 packed-FMA helpers (fallback GEMM) ----------------
__device__ __forceinline__ unsigned long long pk2(float a, float b) {
    unsigned long long r;
    asm("mov.b64 %0, {%1, %2};" : "=l"(r) : "f"(a), "f"(b));
    return r;
}
__device__ __forceinline__ void upk2(unsigned long long v, float& a, float& b) {
    asm("mov.b64 {%0, %1}, %2;" : "=f"(a), "=f"(b) : "l"(v));
}
__device__ __forceinline__ unsigned long long ffma2(unsigned long long a,
                                                    unsigned long long b,
                                                    unsigned long long c) {
    unsigned long long d;
    asm("fma.rn.f32x2 %0, %1, %2, %3;" : "=l"(d) : "l"(a), "l"(b), "l"(c));
    return d;
}

#if TC_OK
// ---------------- tcgen05 macros (arch-specific pass only) ----------------
#define TCGEN05_ALLOC(sm, n) \
    asm volatile("tcgen05.alloc.cta_group::1.sync.aligned.shared::cta.b32 [%0], %1;" \
                 :: "r"(sm), "r"(n) : "memory")
#define TCGEN05_DEALLOC(tm, n) \
    asm volatile("tcgen05.dealloc.cta_group::1.sync.aligned.b32 %0, %1;" :: "r"(tm), "r"(n))
#define TCGEN05_RELINQ() \
    asm volatile("tcgen05.relinquish_alloc_permit.cta_group::1.sync.aligned;")
#define TCGEN05_COMMIT(mb) \
    asm volatile("tcgen05.commit.cta_group::1.mbarrier::arrive::one.shared::cluster.b64 [%0];" \
                 :: "r"(mb) : "memory")
#define TCGEN05_FENCE_BEFORE() asm volatile("tcgen05.fence::before_thread_sync;" ::: "memory")
#define TCGEN05_FENCE_AFTER()  asm volatile("tcgen05.fence::after_thread_sync;" ::: "memory")
#define TCGEN05_WAIT_LD()      asm volatile("tcgen05.wait::ld.sync.aligned;" ::: "memory")
#define FENCE_PROXY_ASYNC()    asm volatile("fence.proxy.async.shared::cta;" ::: "memory")

#define TCGEN05_LD_X16(r, tm)                                                   \
    asm volatile("tcgen05.ld.sync.aligned.32x32b.x16.b32 "                       \
        "{%0, %1, %2, %3, %4, %5, %6, %7, %8, %9, %10, %11, %12, %13, %14, %15}, [%16];" \
        : "=r"((r)[0]), "=r"((r)[1]), "=r"((r)[2]), "=r"((r)[3]),                \
          "=r"((r)[4]), "=r"((r)[5]), "=r"((r)[6]), "=r"((r)[7]),                \
          "=r"((r)[8]), "=r"((r)[9]), "=r"((r)[10]), "=r"((r)[11]),              \
          "=r"((r)[12]), "=r"((r)[13]), "=r"((r)[14]), "=r"((r)[15])             \
        : "r"(tm))

static constexpr uint64_t SMEM_DESC_BASE_SW128 =
    (uint64_t(2) << 61) | (uint64_t(1) << 46) | (uint64_t(64) << 32) | (uint64_t(1) << 16);
__device__ __forceinline__ uint64_t make_desc(uint32_t addr) {
    return SMEM_DESC_BASE_SW128 | ((uint64_t)(addr >> 4) & 0x3FFF);
}

// kind::f16, bf16 A/B, F32 accum, M=128, N=128
#define MMA_IDESC 0x8200490u

__device__ __forceinline__ void mma_bf16_ss(uint32_t d, uint64_t ad, uint64_t bd,
                                            uint32_t enable) {
    asm volatile(
        "{\n\t.reg .pred p;\n\tsetp.ne.u32 p, %4, 0;\n\t"
        "tcgen05.mma.cta_group::1.kind::f16 [%0], %1, %2, %3, {%5, %5, %5, %5}, p;\n\t}"
        :: "r"(d), "l"(ad), "l"(bd), "r"(MMA_IDESC), "r"(enable), "r"(0u) : "memory");
}
#endif // TC_OK

// ---------------- edge-index access (dtype-agnostic) ----------------
__device__ __forceinline__ int load_src(const int* __restrict__ e32, int e, int is64) {
    return is64 ? e32[(size_t)2 * e] : e32[e];
}
__device__ __forceinline__ int load_dst(const int* __restrict__ e32, int e, int is64) {
    return is64 ? e32[(size_t)2 * N_EDGES + (size_t)2 * e] : e32[(size_t)N_EDGES + e];
}

// ---------------- init: zero degree + dtype detect + weight pack (merged) -------------
__global__ void init_pack_kernel(const int* __restrict__ ei32,
                                 const float* __restrict__ W1l, const float* __restrict__ W1r,
                                 const float* __restrict__ W2l, const float* __restrict__ W2r) {
    int idx = blockIdx.x * 256 + threadIdx.x;
    if (idx < N_NODES) g_deg[idx] = 0;
    if (blockIdx.x == 0 && threadIdx.x < 32) {
        int any = 0;
        for (int j = 1 + 2 * (int)threadIdx.x; j < 257; j += 64) any |= ei32[j];
        int anynz = __any_sync(0xffffffffu, any != 0);
        if (threadIdx.x == 0) g_is64 = anynz ? 0 : 1;
    }
    if (idx < 3 * 16384) {
        int which = idx >> 14;
        int e = idx & 16383;
        int k = e >> 7, n = e & 127;
        float w;
        __nv_bfloat16 *hiP, *loP;
        if (which == 0)      { w = W1l[e]; hiP = g_Bp1[0][0]; loP = g_Bp1[0][1]; }
        else if (which == 1) { w = W1r[e]; hiP = g_Bp1[1][0]; loP = g_Bp1[1][1]; }
        else {
            w = (n < 64) ? W2l[k * 64 + n] : W2r[k * 64 + (n - 64)];
            hiP = g_Bp2[0]; loP = g_Bp2[1];
        }
        unsigned off = (unsigned)(((n >> 3) + (k >> 6) * 16) * 1024 + (n & 7) * 128 + (k & 63) * 2);
        unsigned sw = off ^ ((off >> 3) & 0x70);
        __nv_bfloat16 hi = __float2bfloat16_rn(w);
        __nv_bfloat16 lo = __float2bfloat16_rn(w - __bfloat162float(hi));
        hiP[sw >> 1] = hi;
        loP[sw >> 1] = lo;
    }
}

// ---------------- CSR build ----------------
__global__ void hist_kernel(const int* __restrict__ ei32) {
    int e = blockIdx.x * blockDim.x + threadIdx.x;
    if (e < N_EDGES) {
        int d = load_dst(ei32, e, g_is64);
        if ((unsigned)d < N_NODES) atomicAdd(&g_deg[d], 1);
    }
}
__global__ void scan1_kernel() {
    __shared__ int wsum[8], wpre[8];
    int t = threadIdx.x;
    int base = blockIdx.x * 1024 + t * 4;
    int v0 = (base + 0 < N_NODES) ? g_deg[base + 0] : 0;
    int v1 = (base + 1 < N_NODES) ? g_deg[base + 1] : 0;
    int v2 = (base + 2 < N_NODES) ? g_deg[base + 2] : 0;
    int v3 = (base + 3 < N_NODES) ? g_deg[base + 3] : 0;
    int s = v0 + v1 + v2 + v3;
    int lane = t & 31, w = t >> 5;
    int sc = s;
#pragma unroll
    for (int d_ = 1; d_ < 32; d_ <<= 1) {
        int y = __shfl_up_sync(0xffffffffu, sc, d_);
        if (lane >= d_) sc += y;
    }
    if (lane == 31) wsum[w] = sc;
    __syncthreads();
    if (t == 0) {
        int run = 0;
#pragma unroll
        for (int i = 0; i < 8; i++) { int u = wsum[i]; wpre[i] = run; run += u; }
        g_bsums[blockIdx.x] = run;
    }
    __syncthreads();
    int p = wpre[w] + (sc - s);
    if (base + 0 < N_NODES) g_off[base + 0] = p;  p += v0;
    if (base + 1 < N_NODES) g_off[base + 1] = p;  p += v1;
    if (base + 2 < N_NODES) g_off[base + 2] = p;  p += v2;
    if (base + 3 < N_NODES) g_off[base + 3] = p;
}
// scan3m: merged scan2+scan3 — each block warp-reduces its own bsums prefix
__global__ void scan3m_kernel() {
    __shared__ int sadd;
    int t = threadIdx.x;
    if (t < 32) {
        int run = 0;
        for (int i = t; i < (int)blockIdx.x; i += 32) run += g_bsums[i];
#pragma unroll
        for (int d_ = 16; d_; d_ >>= 1) run += __shfl_down_sync(0xffffffffu, run, d_);
        if (t == 0) sadd = run;
    }
    __syncthreads();
    int add = sadd;
    int base = blockIdx.x * 1024 + t * 4;
#pragma unroll
    for (int j = 0; j < 4; j++) {
        int i = base + j;
        if (i < N_NODES) {
            int v = g_off[i] + add;
            g_off[i] = v;
            g_cursor[i] = v;
        }
    }
    if (blockIdx.x == 0 && t == 0) g_off[N_NODES] = N_EDGES;
}
__global__ void build_kernel(const int* __restrict__ ei32) {
    int e = blockIdx.x * blockDim.x + threadIdx.x;
    if (e < N_EDGES) {
        int is64 = g_is64;
        int s = load_src(ei32, e, is64);
        int d = load_dst(ei32, e, is64);
        if ((unsigned)d < N_NODES && (unsigned)s < N_NODES) {
            int p = atomicAdd(&g_cursor[d], 1);
            if ((unsigned)p < N_EDGES) g_csr[p] = s;
        }
    }
}

// ---------------- aggregation 1: mean of fp32 x over in-neighbors, 8-deep MLP --------
__global__ void agg1_kernel(const float* __restrict__ x) {
    int gw = (blockIdx.x * blockDim.x + threadIdx.x) >> 5;
    if (gw >= N_NODES) return;
    int lane = threadIdx.x & 31;
    int col = lane * 4;
    int beg = g_off[gw], end = g_off[gw + 1];
    float4 acc = make_float4(0.f, 0.f, 0.f, 0.f);
    int e = beg;
    for (; e + 7 < end; e += 8) {
        int s0 = g_csr[e],     s1 = g_csr[e + 1], s2 = g_csr[e + 2], s3 = g_csr[e + 3];
        int s4 = g_csr[e + 4], s5 = g_csr[e + 5], s6 = g_csr[e + 6], s7 = g_csr[e + 7];
        float4 a0 = *(const float4*)&x[(size_t)s0 * 128 + col];
        float4 a1 = *(const float4*)&x[(size_t)s1 * 128 + col];
        float4 a2 = *(const float4*)&x[(size_t)s2 * 128 + col];
        float4 a3 = *(const float4*)&x[(size_t)s3 * 128 + col];
        float4 a4 = *(const float4*)&x[(size_t)s4 * 128 + col];
        float4 a5 = *(const float4*)&x[(size_t)s5 * 128 + col];
        float4 a6 = *(const float4*)&x[(size_t)s6 * 128 + col];
        float4 a7 = *(const float4*)&x[(size_t)s7 * 128 + col];
        acc.x += ((a0.x + a1.x) + (a2.x + a3.x)) + ((a4.x + a5.x) + (a6.x + a7.x));
        acc.y += ((a0.y + a1.y) + (a2.y + a3.y)) + ((a4.y + a5.y) + (a6.y + a7.y));
        acc.z += ((a0.z + a1.z) + (a2.z + a3.z)) + ((a4.z + a5.z) + (a6.z + a7.z));
        acc.w += ((a0.w + a1.w) + (a2.w + a3.w)) + ((a4.w + a5.w) + (a6.w + a7.w));
    }
    for (; e < end; e++) {
        int s0 = g_csr[e];
        float4 a = *(const float4*)&x[(size_t)s0 * 128 + col];
        acc.x += a.x; acc.y += a.y; acc.z += a.z; acc.w += a.w;
    }
    int deg = end - beg;
    float inv = 1.f / (float)(deg > 1 ? deg : 1);
    acc.x *= inv; acc.y *= inv; acc.z *= inv; acc.w *= inv;
    *(float4*)&g_mean1[(size_t)gw * 128 + col] = acc;
}

// ---------------- GEMM: three single-phase launches ----------------
// layer 0: R = x@W1r                      -> g_h (raw fp32)   [runs on side stream]
// layer 1: h = relu(mean1@W1l + R + b1)   -> g_h
// layer 2: [t2l(bf16) | t2r(fp32)] = h @ [W2l|W2r]
// Single B buffer (97KB smem -> 2 CTAs/SM), TMEM 128 cols/CTA.
#define SM_TMEMPTR 0
#define SM_MBAR    8
#define SM_AHI     1024
#define SM_ALO     (1024 + 32768)
#define SM_B       (1024 + 65536)
#define GEMM_SMEM  (1024 + 98304)

__global__ __launch_bounds__(256, 2) void gemm_tc_kernel(const float* __restrict__ x,
                                                         const float* __restrict__ W1l,
                                                         const float* __restrict__ W1r,
                                                         const float* __restrict__ b1,
                                                         const float* __restrict__ W2l,
                                                         const float* __restrict__ W2r,
                                                         int layer) {
    extern __shared__ char smem[];
    int t = threadIdx.x;
    int rowBase = blockIdx.x * 128;

#if TC_OK
    (void)W1l; (void)W1r; (void)W2l; (void)W2r;
    uint32_t sb = smem_u32(smem);
    int wid = t >> 5, lane = t & 31;

    if (wid == 0) {
        TCGEN05_ALLOC(sb + SM_TMEMPTR, 128);
        TCGEN05_RELINQ();
    }
    if (t == 0) MBARRIER_INIT(sb + SM_MBAR, 1);
    __syncthreads();
    uint32_t tmem;
    asm volatile("ld.shared.b32 %0, [%1];" : "=r"(tmem) : "r"(sb + SM_TMEMPTR));

    const float* A = (layer == 0) ? x : (layer == 1) ? g_mean1 : g_h;
    const __nv_bfloat16* BpH = (layer == 0) ? g_Bp1[1][0] : (layer == 1) ? g_Bp1[0][0] : g_Bp2[0];
    const __nv_bfloat16* BpL = (layer == 0) ? g_Bp1[1][1] : (layer == 1) ? g_Bp1[0][1] : g_Bp2[1];

    // --- load + split A tile [128 rows x 128 k] fp32 -> bf16 hi/lo, swizzled ---
    {
        int k4 = (t & 31) * 4;
        int rloc = t >> 5;
        unsigned offBase = (unsigned)((k4 >> 6) * 16 * 1024 + (k4 & 63) * 2);
#pragma unroll 4
        for (int it = 0; it < 16; it++) {
            int r = it * 8 + rloc;
            int gr = rowBase + r;
            float4 v = make_float4(0.f, 0.f, 0.f, 0.f);
            if (gr < N_NODES) v = *(const float4*)&A[(size_t)gr * 128 + k4];
            __nv_bfloat16 h0 = __float2bfloat16_rn(v.x);
            __nv_bfloat16 h1 = __float2bfloat16_rn(v.y);
            __nv_bfloat16 h2 = __float2bfloat16_rn(v.z);
            __nv_bfloat16 h3 = __float2bfloat16_rn(v.w);
            __nv_bfloat16 l0 = __float2bfloat16_rn(v.x - __bfloat162float(h0));
            __nv_bfloat16 l1 = __float2bfloat16_rn(v.y - __bfloat162float(h1));
            __nv_bfloat16 l2 = __float2bfloat16_rn(v.z - __bfloat162float(h2));
            __nv_bfloat16 l3 = __float2bfloat16_rn(v.w - __bfloat162float(h3));
            uint2 uh, ul;
            uh.x = (uint32_t)__bfloat16_as_ushort(h0) | ((uint32_t)__bfloat16_as_ushort(h1) << 16);
            uh.y = (uint32_t)__bfloat16_as_ushort(h2) | ((uint32_t)__bfloat16_as_ushort(h3) << 16);
            ul.x = (uint32_t)__bfloat16_as_ushort(l0) | ((uint32_t)__bfloat16_as_ushort(l1) << 16);
            ul.y = (uint32_t)__bfloat16_as_ushort(l2) | ((uint32_t)__bfloat16_as_ushort(l3) << 16);
            unsigned off = offBase + (unsigned)((r >> 3) * 1024 + (r & 7) * 128);
            unsigned sw = off ^ ((off >> 3) & 0x70);
            *(uint2*)(smem + SM_AHI + sw) = uh;
            *(uint2*)(smem + SM_ALO + sw) = ul;
        }
    }
    // --- copy packed B-hi (linear, already swizzled) ---
    {
        const float4* sH = (const float4*)BpH;
        float4* dB = (float4*)(smem + SM_B);
#pragma unroll 8
        for (int i = t; i < 2048; i += 256) dB[i] = sH[i];
    }
    TCGEN05_FENCE_BEFORE();
    __syncthreads();

    if (wid == 0) {
        TCGEN05_FENCE_AFTER();
        FENCE_PROXY_ASYNC();
        if (elect_one()) {
            uint64_t aH = make_desc(sb + SM_AHI);
            uint64_t aL = make_desc(sb + SM_ALO);
            uint64_t bd = make_desc(sb + SM_B);
#pragma unroll
            for (int s = 0; s < 8; s++) {
                uint64_t off = (uint64_t)((s >> 2) * 1024 + (s & 3) * 2);
                mma_bf16_ss(tmem, aH + off, bd + off, (s == 0) ? 0u : 1u);
                mma_bf16_ss(tmem, aL + off, bd + off, 1u);
            }
            TCGEN05_COMMIT(sb + SM_MBAR);
        }
    }
    // wait for MMAs to finish reading B, then overwrite with B-lo
    MBARRIER_WAIT_PARITY(sb + SM_MBAR, 0);
    {
        const float4* sL = (const float4*)BpL;
        float4* dB = (float4*)(smem + SM_B);
#pragma unroll 8
        for (int i = t; i < 2048; i += 256) dB[i] = sL[i];
    }
    TCGEN05_FENCE_BEFORE();
    __syncthreads();
    if (wid == 0) {
        TCGEN05_FENCE_AFTER();
        FENCE_PROXY_ASYNC();
        if (elect_one()) {
            uint64_t aH = make_desc(sb + SM_AHI);
            uint64_t bd = make_desc(sb + SM_B);
#pragma unroll
            for (int s = 0; s < 8; s++) {
                uint64_t off = (uint64_t)((s >> 2) * 1024 + (s & 3) * 2);
                mma_bf16_ss(tmem, aH + off, bd + off, 1u);
            }
            TCGEN05_COMMIT(sb + SM_MBAR);
        }
    }
    MBARRIER_WAIT_PARITY(sb + SM_MBAR, 1);
    TCGEN05_FENCE_AFTER();

    // --- epilogue: warps 0-3 read D (128 rows x 128 cols fp32) ---
    if (wid < 4) {
        int row = rowBase + wid * 32 + lane;
#pragma unroll 1
        for (int j = 0; j < 128; j += 16) {
            uint32_t r[16];
            TCGEN05_LD_X16(r, tmem + (uint32_t)j);
            TCGEN05_WAIT_LD();
            if (row < N_NODES) {
                if (layer == 0) {
                    float* o = &g_h[(size_t)row * 128 + j];
                    *(float4*)(o + 0)  = make_float4(__uint_as_float(r[0]),  __uint_as_float(r[1]),
                                                     __uint_as_float(r[2]),  __uint_as_float(r[3]));
                    *(float4*)(o + 4)  = make_float4(__uint_as_float(r[4]),  __uint_as_float(r[5]),
                                                     __uint_as_float(r[6]),  __uint_as_float(r[7]));
                    *(float4*)(o + 8)  = make_float4(__uint_as_float(r[8]),  __uint_as_float(r[9]),
                                                     __uint_as_float(r[10]), __uint_as_float(r[11]));
                    *(float4*)(o + 12) = make_float4(__uint_as_float(r[12]), __uint_as_float(r[13]),
                                                     __uint_as_float(r[14]), __uint_as_float(r[15]));
                } else if (layer == 1) {
                    float* o = &g_h[(size_t)row * 128 + j];
                    float4 R0 = *(const float4*)(o + 0);
                    float4 R1 = *(const float4*)(o + 4);
                    float4 R2 = *(const float4*)(o + 8);
                    float4 R3 = *(const float4*)(o + 12);
                    float Rv[16] = {R0.x, R0.y, R0.z, R0.w, R1.x, R1.y, R1.z, R1.w,
                                    R2.x, R2.y, R2.z, R2.w, R3.x, R3.y, R3.z, R3.w};
                    float v[16];
#pragma unroll
                    for (int c = 0; c < 16; c++)
                        v[c] = fmaxf(__uint_as_float(r[c]) + Rv[c] + b1[j + c], 0.f);
                    *(float4*)(o + 0)  = make_float4(v[0], v[1], v[2], v[3]);
                    *(float4*)(o + 4)  = make_float4(v[4], v[5], v[6], v[7]);
                    *(float4*)(o + 8)  = make_float4(v[8], v[9], v[10], v[11]);
                    *(float4*)(o + 12) = make_float4(v[12], v[13], v[14], v[15]);
                } else if (j < 64) {
                    uint4 u0, u1;
                    uint32_t* uu[8] = {&u0.x, &u0.y, &u0.z, &u0.w, &u1.x, &u1.y, &u1.z, &u1.w};
#pragma unroll
                    for (int p2 = 0; p2 < 8; p2++) {
                        __nv_bfloat16 a = __float2bfloat16_rn(__uint_as_float(r[p2 * 2]));
                        __nv_bfloat16 b = __float2bfloat16_rn(__uint_as_float(r[p2 * 2 + 1]));
                        *uu[p2] = (uint32_t)__bfloat16_as_ushort(a) |
                                  ((uint32_t)__bfloat16_as_ushort(b) << 16);
                    }
                    __nv_bfloat16* o = &g_t2l[(size_t)row * 64 + j];
                    *(uint4*)(o + 0) = u0;
                    *(uint4*)(o + 8) = u1;
                } else {
                    float* o = &g_t2r[(size_t)row * 64 + (j - 64)];
                    *(float4*)(o + 0)  = make_float4(__uint_as_float(r[0]),  __uint_as_float(r[1]),
                                                     __uint_as_float(r[2]),  __uint_as_float(r[3]));
                    *(float4*)(o + 4)  = make_float4(__uint_as_float(r[4]),  __uint_as_float(r[5]),
                                                     __uint_as_float(r[6]),  __uint_as_float(r[7]));
                    *(float4*)(o + 8)  = make_float4(__uint_as_float(r[8]),  __uint_as_float(r[9]),
                                                     __uint_as_float(r[10]), __uint_as_float(r[11]));
                    *(float4*)(o + 12) = make_float4(__uint_as_float(r[12]), __uint_as_float(r[13]),
                                                     __uint_as_float(r[14]), __uint_as_float(r[15]));
                }
            }
        }
    }
    __syncthreads();
    if (t == 0) {
        asm volatile("mbarrier.inval.shared.b64 [%0];" :: "r"(sb + SM_MBAR) : "memory");
    }
    if (wid == 0) TCGEN05_DEALLOC(tmem, 128);

#else  // ---------------- SIMT f32x2 fallback (base-arch compilation) ----------------
    float* As = (float*)smem;               // [128][16]
    float* Ws = (float*)(smem + 8192);      // [16][128]
    int tx = t & 15;
    int ty = t >> 4;

    unsigned long long acc[8][4];
#pragma unroll
    for (int r = 0; r < 8; r++)
#pragma unroll
        for (int c = 0; c < 4; c++) acc[r][c] = 0ull;

    const float* Af = (layer == 0) ? x : (layer == 1) ? g_mean1 : g_h;
#pragma unroll 1
    for (int kc = 0; kc < 128; kc += 16) {
        __syncthreads();
#pragma unroll
        for (int i = 0; i < 2; i++) {
            int idx = t + i * 256;
            int row = idx >> 2;
            int k4 = (idx & 3) << 2;
            int gr = rowBase + row;
            float4 v = make_float4(0.f, 0.f, 0.f, 0.f);
            if (gr < N_NODES) v = *(const float4*)&Af[(size_t)gr * 128 + kc + k4];
            *(float4*)&As[row * 16 + k4] = v;
        }
#pragma unroll
        for (int i = 0; i < 2; i++) {
            int idx = t + i * 256;
            int k = idx >> 5;
            int j4 = (idx & 31) << 2;
            float4 v;
            if (layer == 0)      v = *(const float4*)&W1r[(kc + k) * 128 + j4];
            else if (layer == 1) v = *(const float4*)&W1l[(kc + k) * 128 + j4];
            else {
                if (j4 < 64) v = *(const float4*)&W2l[(kc + k) * 64 + j4];
                else         v = *(const float4*)&W2r[(kc + k) * 64 + (j4 - 64)];
            }
            *(float4*)&Ws[k * 128 + j4] = v;
        }
        __syncthreads();
#pragma unroll
        for (int k = 0; k < 16; k++) {
            float4 blo = *(const float4*)&Ws[k * 128 + tx * 8];
            float4 bhi = *(const float4*)&Ws[k * 128 + tx * 8 + 4];
            unsigned long long bp0 = pk2(blo.x, blo.y);
            unsigned long long bp1 = pk2(blo.z, blo.w);
            unsigned long long bp2 = pk2(bhi.x, bhi.y);
            unsigned long long bp3 = pk2(bhi.z, bhi.w);
#pragma unroll
            for (int r = 0; r < 8; r++) {
                float a = As[(ty * 8 + r) * 16 + k];
                unsigned long long a2 = pk2(a, a);
                acc[r][0] = ffma2(a2, bp0, acc[r][0]);
                acc[r][1] = ffma2(a2, bp1, acc[r][1]);
                acc[r][2] = ffma2(a2, bp2, acc[r][2]);
                acc[r][3] = ffma2(a2, bp3, acc[r][3]);
            }
        }
    }
#pragma unroll
    for (int r = 0; r < 8; r++) {
        int row = rowBase + ty * 8 + r;
        if (row < N_NODES) {
#pragma unroll
            for (int c = 0; c < 4; c++) {
                float f0, f1;
                upk2(acc[r][c], f0, f1);
                int j = tx * 8 + c * 2;
                if (layer == 0) {
                    *(float2*)&g_h[(size_t)row * 128 + j] = make_float2(f0, f1);
                } else if (layer == 1) {
                    float2 R = *(const float2*)&g_h[(size_t)row * 128 + j];
                    f0 = fmaxf(f0 + R.x + b1[j], 0.f);
                    f1 = fmaxf(f1 + R.y + b1[j + 1], 0.f);
                    *(float2*)&g_h[(size_t)row * 128 + j] = make_float2(f0, f1);
                } else if (j < 64) {
                    uint32_t u = (uint32_t)__bfloat16_as_ushort(__float2bfloat16_rn(f0)) |
                                 ((uint32_t)__bfloat16_as_ushort(__float2bfloat16_rn(f1)) << 16);
                    *(uint32_t*)&g_t2l[(size_t)row * 64 + j] = u;
                } else {
                    *(float2*)&g_t2r[(size_t)row * 64 + (j - 64)] = make_float2(f0, f1);
                }
            }
        }
    }
#endif // TC_OK
}

// ---------------- aggregation 2 + epilogue, 8-deep MLP ----------------
// z = relu(segment_mean(t2l) + t2r[self] + b2)
__global__ void agg2_kernel(const float* __restrict__ b2, float* __restrict__ out) {
    int gw = (blockIdx.x * blockDim.x + threadIdx.x) >> 5;
    if (gw >= N_NODES) return;
    int lane = threadIdx.x & 31;
    int col = lane * 2;
    int beg = g_off[gw], end = g_off[gw + 1];
    float2 acc = make_float2(0.f, 0.f);
    int e = beg;
    for (; e + 7 < end; e += 8) {
        uint32_t u[8];
#pragma unroll
        for (int q = 0; q < 8; q++)
            u[q] = *(const uint32_t*)&g_t2l[(size_t)g_csr[e + q] * 64 + col];
        float2 s0 = make_float2(0.f, 0.f), s1 = make_float2(0.f, 0.f);
#pragma unroll
        for (int q = 0; q < 8; q += 2) {
            float2 f0 = __bfloat1622float2(*(__nv_bfloat162*)&u[q]);
            float2 f1 = __bfloat1622float2(*(__nv_bfloat162*)&u[q + 1]);
            s0.x += f0.x; s0.y += f0.y;
            s1.x += f1.x; s1.y += f1.y;
        }
        acc.x += s0.x + s1.x;
        acc.y += s0.y + s1.y;
    }
    for (; e < end; e++) {
        uint32_t u = *(const uint32_t*)&g_t2l[(size_t)g_csr[e] * 64 + col];
        float2 f = __bfloat1622float2(*(__nv_bfloat162*)&u);
        acc.x += f.x; acc.y += f.y;
    }
    int deg = end - beg;
    float inv = 1.f / (float)(deg > 1 ? deg : 1);
    float2 rr = *(const float2*)&g_t2r[(size_t)gw * 64 + col];
    float o0 = fmaxf(acc.x * inv + rr.x + b2[col], 0.f);
    float o1 = fmaxf(acc.y * inv + rr.y + b2[col + 1], 0.f);
    *(float2*)&out[(size_t)gw * 64 + col] = make_float2(o0, o1);
}

// ---------------- launch ----------------
extern "C" void kernel_launch(void* const* d_in, const int* in_sizes, int n_in,
                              void* d_out, int out_size) {
    const float* x   = (const float*)d_in[0];
    const int*   ei  = (const int*)d_in[1];
    const float* W1l = (const float*)d_in[2];
    const float* W1r = (const float*)d_in[3];
    const float* b1  = (const float*)d_in[4];
    const float* W2l = (const float*)d_in[5];
    const float* W2r = (const float*)d_in[6];
    const float* b2  = (const float*)d_in[7];
    float* out = (float*)d_out;

    (void)in_sizes; (void)n_in; (void)out_size;

    cudaFuncSetAttribute(gemm_tc_kernel, cudaFuncAttributeMaxDynamicSharedMemorySize,
                         GEMM_SMEM);

    const int NB_SCAN = (N_NODES + 1023) / 1024;       // 98
    const int EB      = (N_EDGES + 255) / 256;         // 6250
    const int GEMMB   = (N_NODES + 127) / 128;         // 782
    const int AGGB    = (N_NODES + 7) / 8;             // 12500

    // stream 0 (captured origin): init, then CSR chain + agg1
    init_pack_kernel<<<(N_NODES + 255) / 256, 256>>>(ei, W1l, W1r, W2l, W2r);

    // fork: side stream computes R = x@W1r (depends only on init_pack)
    cudaEventRecord(g_infra.evFork, 0);
    cudaStreamWaitEvent(g_infra.s1, g_infra.evFork, 0);
    gemm_tc_kernel<<<GEMMB, 256, GEMM_SMEM, g_infra.s1>>>(x, W1l, W1r, b1, W2l, W2r, 0);
    cudaEventRecord(g_infra.evJoin, g_infra.s1);

    // main branch: CSR build + aggregation 1
    hist_kernel<<<EB, 256>>>(ei);
    scan1_kernel<<<NB_SCAN, 256>>>();
    scan3m_kernel<<<NB_SCAN, 256>>>();
    build_kernel<<<EB, 256>>>(ei);
    agg1_kernel<<<AGGB, 256>>>(x);

    // join: layer-1 GEMM needs both agg1 (mean1) and R (g_h)
    cudaStreamWaitEvent(0, g_infra.evJoin, 0);
    gemm_tc_kernel<<<GEMMB, 256, GEMM_SMEM>>>(x, W1l, W1r, b1, W2l, W2r, 1);
    gemm_tc_kernel<<<GEMMB, 256, GEMM_SMEM>>>(x, W1l, W1r, b1, W2l, W2r, 2);
    agg2_kernel<<<AGGB, 256>>>(b2, out);
}

// round 15
// speedup vs baseline: 1.5657x; 1.5657x over previous
#include <cuda_runtime.h>
#include <cuda_bf16.h>
#include <cstdint>

#define N_NODES 100000
#define N_EDGES 1600000
#define D_IN 128
#define D_HID 128
#define D_LAT 64

// tcgen05 is arch-SPECIFIC (sm_103a / sm_100a). The harness also compiles a
// base-family compute_103 target, which rejects tcgen05 — so every tcgen05 use
// is gated on the arch-specific feature macros, with a SIMT fallback body.
#if !defined(__CUDA_ARCH__)
#define TC_OK 1   /* host pass: declarations only, nothing codegen'd */
#elif defined(__CUDA_ARCH_FEAT_SM103_ALL) || defined(__CUDA_ARCH_FEAT_SM100_ALL) || \
      (defined(__CUDA_ARCH_SPECIFIC__) && (__CUDA_ARCH_SPECIFIC__ >= 1000))
#define TC_OK 1
#else
#define TC_OK 0
#endif

// ---------------- scratch (static device globals; no allocation) ----------------
__device__ int   g_is64;
__device__ int   g_deg[N_NODES];
__device__ int   g_off[N_NODES + 1];
__device__ int   g_cursor[N_NODES];
__device__ int   g_bsums[128];
__device__ int   g_csr[N_EDGES];
__device__ float g_mean1[(size_t)N_NODES * 128];          // mean-aggregated x (fp32)
__device__ float g_h[(size_t)N_NODES * 128];              // layer-1 output
__device__ __nv_bfloat16 g_t2l[(size_t)N_NODES * 64];     // h@W2_l (bf16, gather source)
__device__ float g_t2r[(size_t)N_NODES * 64];             // h@W2_r (fp32, self path)

// packed weight tiles: exact SW128-swizzled SMEM byte image, [hi|lo] bf16
__device__ __nv_bfloat16 g_Bp1[2][2][16384];   // [phase(W1l/W1r)][hi/lo]
__device__ __nv_bfloat16 g_Bp2[2][16384];      // [hi/lo] concat(W2l|W2r)

// ---------------- small PTX helpers (arch-portable) ----------------
__device__ __forceinline__ uint32_t smem_u32(const void* p) {
    uint32_t a;
    asm("{ .reg .u64 t; cvta.to.shared.u64 t, %1; cvt.u32.u64 %0, t; }" : "=r"(a) : "l"(p));
    return a;
}
__device__ __forceinline__ uint32_t elect_one() {
    uint32_t pred;
    asm volatile("{\n\t.reg .pred p;\n\telect.sync _|p, 0xFFFFFFFF;\n\tselp.b32 %0, 1, 0, p;\n\t}"
                 : "=r"(pred));
    return pred;
}

#define MBARRIER_INIT(addr, cnt) \
    asm volatile("mbarrier.init.shared.b64 [%0], %1;" :: "r"(addr), "r"(cnt) : "memory")

#define MBARRIER_WAIT_PARITY(addr, par) do {                                            \
    uint32_t _m = (addr), _p = (par), _d;                                               \
    asm volatile("{\n\t.reg .pred p;\n\t"                                               \
        "mbarrier.try_wait.parity.acquire.cta.shared::cta.b64 p, [%1], %2;\n\t"          \
        "selp.b32 %0, 1, 0, p;\n\t}" : "=r"(_d) : "r"(_m), "r"(_p) : "memory");          \
    if (!_d) {                                                                           \
        asm volatile("{\n\t.reg .pred P1;\n\t"                                           \
            "WL_%=:\n\t"                                                                 \
            "mbarrier.try_wait.parity.acquire.cta.shared::cta.b64 P1, [%0], %1, 0x989680;\n\t" \
            "@P1 bra.uni WD_%=;\n\t"                                                     \
            "bra.uni WL_%=;\n\t"                                                         \
            "WD_%=:\n\t}" :: "r"(_m), "r"(_p) : "memory");                               \
    }                                                                                    \
} while (0)

// ---------------- f32x2 packed-FMA helpers (fallback GEMM) ----------------
__device__ __forceinline__ unsigned long long pk2(float a, float b) {
    unsigned long long r;
    asm("mov.b64 %0, {%1, %2};" : "=l"(r) : "f"(a), "f"(b));
    return r;
}
__device__ __forceinline__ void upk2(unsigned long long v, float& a, float& b) {
    asm("mov.b64 {%0, %1}, %2;" : "=f"(a), "=f"(b) : "l"(v));
}
__device__ __forceinline__ unsigned long long ffma2(unsigned long long a,
                                                    unsigned long long b,
                                                    unsigned long long c) {
    unsigned long long d;
    asm("fma.rn.f32x2 %0, %1, %2, %3;" : "=l"(d) : "l"(a), "l"(b), "l"(c));
    return d;
}

#if TC_OK
// ---------------- tcgen05 macros (arch-specific pass only) ----------------
#define TCGEN05_ALLOC(sm, n) \
    asm volatile("tcgen05.alloc.cta_group::1.sync.aligned.shared::cta.b32 [%0], %1;" \
                 :: "r"(sm), "r"(n) : "memory")
#define TCGEN05_DEALLOC(tm, n) \
    asm volatile("tcgen05.dealloc.cta_group::1.sync.aligned.b32 %0, %1;" :: "r"(tm), "r"(n))
#define TCGEN05_RELINQ() \
    asm volatile("tcgen05.relinquish_alloc_permit.cta_group::1.sync.aligned;")
#define TCGEN05_COMMIT(mb) \
    asm volatile("tcgen05.commit.cta_group::1.mbarrier::arrive::one.shared::cluster.b64 [%0];" \
                 :: "r"(mb) : "memory")
#define TCGEN05_FENCE_BEFORE() asm volatile("tcgen05.fence::before_thread_sync;" ::: "memory")
#define TCGEN05_FENCE_AFTER()  asm volatile("tcgen05.fence::after_thread_sync;" ::: "memory")
#define TCGEN05_WAIT_LD()      asm volatile("tcgen05.wait::ld.sync.aligned;" ::: "memory")
#define FENCE_PROXY_ASYNC()    asm volatile("fence.proxy.async.shared::cta;" ::: "memory")

#define TCGEN05_LD_X16(r, tm)                                                   \
    asm volatile("tcgen05.ld.sync.aligned.32x32b.x16.b32 "                       \
        "{%0, %1, %2, %3, %4, %5, %6, %7, %8, %9, %10, %11, %12, %13, %14, %15}, [%16];" \
        : "=r"((r)[0]), "=r"((r)[1]), "=r"((r)[2]), "=r"((r)[3]),                \
          "=r"((r)[4]), "=r"((r)[5]), "=r"((r)[6]), "=r"((r)[7]),                \
          "=r"((r)[8]), "=r"((r)[9]), "=r"((r)[10]), "=r"((r)[11]),              \
          "=r"((r)[12]), "=r"((r)[13]), "=r"((r)[14]), "=r"((r)[15])             \
        : "r"(tm))

static constexpr uint64_t SMEM_DESC_BASE_SW128 =
    (uint64_t(2) << 61) | (uint64_t(1) << 46) | (uint64_t(64) << 32) | (uint64_t(1) << 16);
__device__ __forceinline__ uint64_t make_desc(uint32_t addr) {
    return SMEM_DESC_BASE_SW128 | ((uint64_t)(addr >> 4) & 0x3FFF);
}

// kind::f16, bf16 A/B, F32 accum, M=128, N=128
#define MMA_IDESC 0x8200490u

__device__ __forceinline__ void mma_bf16_ss(uint32_t d, uint64_t ad, uint64_t bd,
                                            uint32_t enable) {
    asm volatile(
        "{\n\t.reg .pred p;\n\tsetp.ne.u32 p, %4, 0;\n\t"
        "tcgen05.mma.cta_group::1.kind::f16 [%0], %1, %2, %3, {%5, %5, %5, %5}, p;\n\t}"
        :: "r"(d), "l"(ad), "l"(bd), "r"(MMA_IDESC), "r"(enable), "r"(0u) : "memory");
}
#endif // TC_OK

// ---------------- edge-index access (dtype-agnostic) ----------------
__device__ __forceinline__ int load_src(const int* __restrict__ e32, int e, int is64) {
    return is64 ? e32[(size_t)2 * e] : e32[e];
}
__device__ __forceinline__ int load_dst(const int* __restrict__ e32, int e, int is64) {
    return is64 ? e32[(size_t)2 * N_EDGES + (size_t)2 * e] : e32[(size_t)N_EDGES + e];
}

// ---------------- init: zero degree + dtype detect + weight pack (merged) -------------
__global__ void init_pack_kernel(const int* __restrict__ ei32,
                                 const float* __restrict__ W1l, const float* __restrict__ W1r,
                                 const float* __restrict__ W2l, const float* __restrict__ W2r) {
    int idx = blockIdx.x * 256 + threadIdx.x;
    if (idx < N_NODES) g_deg[idx] = 0;
    if (blockIdx.x == 0 && threadIdx.x < 32) {
        int any = 0;
        for (int j = 1 + 2 * (int)threadIdx.x; j < 257; j += 64) any |= ei32[j];
        int anynz = __any_sync(0xffffffffu, any != 0);
        if (threadIdx.x == 0) g_is64 = anynz ? 0 : 1;
    }
    if (idx < 3 * 16384) {
        int which = idx >> 14;
        int e = idx & 16383;
        int k = e >> 7, n = e & 127;
        float w;
        __nv_bfloat16 *hiP, *loP;
        if (which == 0)      { w = W1l[e]; hiP = g_Bp1[0][0]; loP = g_Bp1[0][1]; }
        else if (which == 1) { w = W1r[e]; hiP = g_Bp1[1][0]; loP = g_Bp1[1][1]; }
        else {
            w = (n < 64) ? W2l[k * 64 + n] : W2r[k * 64 + (n - 64)];
            hiP = g_Bp2[0]; loP = g_Bp2[1];
        }
        unsigned off = (unsigned)(((n >> 3) + (k >> 6) * 16) * 1024 + (n & 7) * 128 + (k & 63) * 2);
        unsigned sw = off ^ ((off >> 3) & 0x70);
        __nv_bfloat16 hi = __float2bfloat16_rn(w);
        __nv_bfloat16 lo = __float2bfloat16_rn(w - __bfloat162float(hi));
        hiP[sw >> 1] = hi;
        loP[sw >> 1] = lo;
    }
}

// ---------------- CSR build ----------------
__global__ void hist_kernel(const int* __restrict__ ei32) {
    int e = blockIdx.x * blockDim.x + threadIdx.x;
    if (e < N_EDGES) {
        int d = load_dst(ei32, e, g_is64);
        if ((unsigned)d < N_NODES) atomicAdd(&g_deg[d], 1);
    }
}
__global__ void scan1_kernel() {
    __shared__ int wsum[8], wpre[8];
    int t = threadIdx.x;
    int base = blockIdx.x * 1024 + t * 4;
    int v0 = (base + 0 < N_NODES) ? g_deg[base + 0] : 0;
    int v1 = (base + 1 < N_NODES) ? g_deg[base + 1] : 0;
    int v2 = (base + 2 < N_NODES) ? g_deg[base + 2] : 0;
    int v3 = (base + 3 < N_NODES) ? g_deg[base + 3] : 0;
    int s = v0 + v1 + v2 + v3;
    int lane = t & 31, w = t >> 5;
    int sc = s;
#pragma unroll
    for (int d_ = 1; d_ < 32; d_ <<= 1) {
        int y = __shfl_up_sync(0xffffffffu, sc, d_);
        if (lane >= d_) sc += y;
    }
    if (lane == 31) wsum[w] = sc;
    __syncthreads();
    if (t == 0) {
        int run = 0;
#pragma unroll
        for (int i = 0; i < 8; i++) { int u = wsum[i]; wpre[i] = run; run += u; }
        g_bsums[blockIdx.x] = run;
    }
    __syncthreads();
    int p = wpre[w] + (sc - s);
    if (base + 0 < N_NODES) g_off[base + 0] = p;  p += v0;
    if (base + 1 < N_NODES) g_off[base + 1] = p;  p += v1;
    if (base + 2 < N_NODES) g_off[base + 2] = p;  p += v2;
    if (base + 3 < N_NODES) g_off[base + 3] = p;
}
// scan3m: merged scan2+scan3 — each block warp-reduces its own bsums prefix
__global__ void scan3m_kernel() {
    __shared__ int sadd;
    int t = threadIdx.x;
    if (t < 32) {
        int run = 0;
        for (int i = t; i < (int)blockIdx.x; i += 32) run += g_bsums[i];
#pragma unroll
        for (int d_ = 16; d_; d_ >>= 1) run += __shfl_down_sync(0xffffffffu, run, d_);
        if (t == 0) sadd = run;
    }
    __syncthreads();
    int add = sadd;
    int base = blockIdx.x * 1024 + t * 4;
#pragma unroll
    for (int j = 0; j < 4; j++) {
        int i = base + j;
        if (i < N_NODES) {
            int v = g_off[i] + add;
            g_off[i] = v;
            g_cursor[i] = v;
        }
    }
    if (blockIdx.x == 0 && t == 0) g_off[N_NODES] = N_EDGES;
}
__global__ void build_kernel(const int* __restrict__ ei32) {
    int e = blockIdx.x * blockDim.x + threadIdx.x;
    if (e < N_EDGES) {
        int is64 = g_is64;
        int s = load_src(ei32, e, is64);
        int d = load_dst(ei32, e, is64);
        if ((unsigned)d < N_NODES && (unsigned)s < N_NODES) {
            int p = atomicAdd(&g_cursor[d], 1);
            if ((unsigned)p < N_EDGES) g_csr[p] = s;
        }
    }
}

// ---------------- aggregation 1: mean of fp32 x over in-neighbors, 8-deep MLP --------
__global__ void agg1_kernel(const float* __restrict__ x) {
    int gw = (blockIdx.x * blockDim.x + threadIdx.x) >> 5;
    if (gw >= N_NODES) return;
    int lane = threadIdx.x & 31;
    int col = lane * 4;
    int beg = g_off[gw], end = g_off[gw + 1];
    float4 acc = make_float4(0.f, 0.f, 0.f, 0.f);
    int e = beg;
    for (; e + 7 < end; e += 8) {
        int s0 = g_csr[e],     s1 = g_csr[e + 1], s2 = g_csr[e + 2], s3 = g_csr[e + 3];
        int s4 = g_csr[e + 4], s5 = g_csr[e + 5], s6 = g_csr[e + 6], s7 = g_csr[e + 7];
        float4 a0 = *(const float4*)&x[(size_t)s0 * 128 + col];
        float4 a1 = *(const float4*)&x[(size_t)s1 * 128 + col];
        float4 a2 = *(const float4*)&x[(size_t)s2 * 128 + col];
        float4 a3 = *(const float4*)&x[(size_t)s3 * 128 + col];
        float4 a4 = *(const float4*)&x[(size_t)s4 * 128 + col];
        float4 a5 = *(const float4*)&x[(size_t)s5 * 128 + col];
        float4 a6 = *(const float4*)&x[(size_t)s6 * 128 + col];
        float4 a7 = *(const float4*)&x[(size_t)s7 * 128 + col];
        acc.x += ((a0.x + a1.x) + (a2.x + a3.x)) + ((a4.x + a5.x) + (a6.x + a7.x));
        acc.y += ((a0.y + a1.y) + (a2.y + a3.y)) + ((a4.y + a5.y) + (a6.y + a7.y));
        acc.z += ((a0.z + a1.z) + (a2.z + a3.z)) + ((a4.z + a5.z) + (a6.z + a7.z));
        acc.w += ((a0.w + a1.w) + (a2.w + a3.w)) + ((a4.w + a5.w) + (a6.w + a7.w));
    }
    for (; e < end; e++) {
        int s0 = g_csr[e];
        float4 a = *(const float4*)&x[(size_t)s0 * 128 + col];
        acc.x += a.x; acc.y += a.y; acc.z += a.z; acc.w += a.w;
    }
    int deg = end - beg;
    float inv = 1.f / (float)(deg > 1 ? deg : 1);
    acc.x *= inv; acc.y *= inv; acc.z *= inv; acc.w *= inv;
    *(float4*)&g_mean1[(size_t)gw * 128 + col] = acc;
}

// ---------------- GEMM (both layers): tcgen05 on sm_103a, SIMT f32x2 otherwise --------
// layer==1: h = relu(mean1@W1l + x@W1r + b1)            (2 phases)
// layer==2: [t2l(bf16) | t2r(fp32)] = h @ [W2l|W2r]     (1 phase)
// Single B buffer (97KB smem -> 2 CTAs/SM), TMEM 128 cols/CTA (2x128=256 < 512 cap).
#define SM_TMEMPTR 0
#define SM_MBAR    8
#define SM_AHI     1024
#define SM_ALO     (1024 + 32768)
#define SM_B       (1024 + 65536)
#define GEMM_SMEM  (1024 + 98304)

__global__ __launch_bounds__(256, 2) void gemm_tc_kernel(const float* __restrict__ x,
                                                         const float* __restrict__ W1l,
                                                         const float* __restrict__ W1r,
                                                         const float* __restrict__ b1,
                                                         const float* __restrict__ W2l,
                                                         const float* __restrict__ W2r,
                                                         int layer) {
    extern __shared__ char smem[];
    int t = threadIdx.x;
    int rowBase = blockIdx.x * 128;
    int nPhases = (layer == 1) ? 2 : 1;

#if TC_OK
    (void)W1l; (void)W1r; (void)W2l; (void)W2r;
    uint32_t sb = smem_u32(smem);
    int wid = t >> 5, lane = t & 31;

    if (wid == 0) {
        TCGEN05_ALLOC(sb + SM_TMEMPTR, 128);
        TCGEN05_RELINQ();
    }
    if (t == 0) MBARRIER_INIT(sb + SM_MBAR, 1);
    __syncthreads();
    uint32_t tmem;
    asm volatile("ld.shared.b32 %0, [%1];" : "=r"(tmem) : "r"(sb + SM_TMEMPTR));

    uint32_t first = 1;
    int wpar = 0;
    for (int ph = 0; ph < nPhases; ph++) {
        const float* A = (layer == 1) ? (ph == 0 ? g_mean1 : x) : g_h;
        const __nv_bfloat16* BpH = (layer == 1) ? g_Bp1[ph][0] : g_Bp2[0];
        const __nv_bfloat16* BpL = (layer == 1) ? g_Bp1[ph][1] : g_Bp2[1];

        if (ph > 0) { MBARRIER_WAIT_PARITY(sb + SM_MBAR, wpar); wpar ^= 1; }

        // --- load + split A tile [128 rows x 128 k] fp32 -> bf16 hi/lo, swizzled ---
        {
            int k4 = (t & 31) * 4;
            int rloc = t >> 5;
            unsigned offBase = (unsigned)((k4 >> 6) * 16 * 1024 + (k4 & 63) * 2);
#pragma unroll 4
            for (int it = 0; it < 16; it++) {
                int r = it * 8 + rloc;
                int gr = rowBase + r;
                float4 v = make_float4(0.f, 0.f, 0.f, 0.f);
                if (gr < N_NODES) v = *(const float4*)&A[(size_t)gr * 128 + k4];
                __nv_bfloat16 h0 = __float2bfloat16_rn(v.x);
                __nv_bfloat16 h1 = __float2bfloat16_rn(v.y);
                __nv_bfloat16 h2 = __float2bfloat16_rn(v.z);
                __nv_bfloat16 h3 = __float2bfloat16_rn(v.w);
                __nv_bfloat16 l0 = __float2bfloat16_rn(v.x - __bfloat162float(h0));
                __nv_bfloat16 l1 = __float2bfloat16_rn(v.y - __bfloat162float(h1));
                __nv_bfloat16 l2 = __float2bfloat16_rn(v.z - __bfloat162float(h2));
                __nv_bfloat16 l3 = __float2bfloat16_rn(v.w - __bfloat162float(h3));
                uint2 uh, ul;
                uh.x = (uint32_t)__bfloat16_as_ushort(h0) | ((uint32_t)__bfloat16_as_ushort(h1) << 16);
                uh.y = (uint32_t)__bfloat16_as_ushort(h2) | ((uint32_t)__bfloat16_as_ushort(h3) << 16);
                ul.x = (uint32_t)__bfloat16_as_ushort(l0) | ((uint32_t)__bfloat16_as_ushort(l1) << 16);
                ul.y = (uint32_t)__bfloat16_as_ushort(l2) | ((uint32_t)__bfloat16_as_ushort(l3) << 16);
                unsigned off = offBase + (unsigned)((r >> 3) * 1024 + (r & 7) * 128);
                unsigned sw = off ^ ((off >> 3) & 0x70);
                *(uint2*)(smem + SM_AHI + sw) = uh;
                *(uint2*)(smem + SM_ALO + sw) = ul;
            }
        }
        // --- copy packed B-hi (linear, already swizzled) ---
        {
            const float4* sH = (const float4*)BpH;
            float4* dB = (float4*)(smem + SM_B);
#pragma unroll 8
            for (int i = t; i < 2048; i += 256) dB[i] = sH[i];
        }
        TCGEN05_FENCE_BEFORE();
        __syncthreads();

        if (wid == 0) {
            TCGEN05_FENCE_AFTER();
            FENCE_PROXY_ASYNC();
            if (elect_one()) {
                uint64_t aH = make_desc(sb + SM_AHI);
                uint64_t aL = make_desc(sb + SM_ALO);
                uint64_t bd = make_desc(sb + SM_B);
#pragma unroll
                for (int s = 0; s < 8; s++) {
                    uint64_t off = (uint64_t)((s >> 2) * 1024 + (s & 3) * 2);
                    mma_bf16_ss(tmem, aH + off, bd + off, first ? 0u : 1u);
                    first = 0;
                    mma_bf16_ss(tmem, aL + off, bd + off, 1u);
                }
                TCGEN05_COMMIT(sb + SM_MBAR);
            }
        }
        // wait for MMAs to finish reading B, then overwrite with B-lo
        MBARRIER_WAIT_PARITY(sb + SM_MBAR, wpar); wpar ^= 1;
        {
            const float4* sL = (const float4*)BpL;
            float4* dB = (float4*)(smem + SM_B);
#pragma unroll 8
            for (int i = t; i < 2048; i += 256) dB[i] = sL[i];
        }
        TCGEN05_FENCE_BEFORE();
        __syncthreads();
        if (wid == 0) {
            TCGEN05_FENCE_AFTER();
            FENCE_PROXY_ASYNC();
            if (elect_one()) {
                uint64_t aH = make_desc(sb + SM_AHI);
                uint64_t bd = make_desc(sb + SM_B);
#pragma unroll
                for (int s = 0; s < 8; s++) {
                    uint64_t off = (uint64_t)((s >> 2) * 1024 + (s & 3) * 2);
                    mma_bf16_ss(tmem, aH + off, bd + off, 1u);
                }
                TCGEN05_COMMIT(sb + SM_MBAR);
            }
        }
        __syncthreads();
    }

    MBARRIER_WAIT_PARITY(sb + SM_MBAR, wpar); wpar ^= 1;
    TCGEN05_FENCE_AFTER();

    // --- epilogue: warps 0-3 read D (128 rows x 128 cols fp32) ---
    if (wid < 4) {
        int row = rowBase + wid * 32 + lane;
#pragma unroll 1
        for (int j = 0; j < 128; j += 16) {
            uint32_t r[16];
            TCGEN05_LD_X16(r, tmem + (uint32_t)j);
            TCGEN05_WAIT_LD();
            if (row < N_NODES) {
                if (layer == 1) {
                    float v[16];
#pragma unroll
                    for (int c = 0; c < 16; c++)
                        v[c] = fmaxf(__uint_as_float(r[c]) + b1[j + c], 0.f);
                    float* o = &g_h[(size_t)row * 128 + j];
                    *(float4*)(o + 0)  = make_float4(v[0], v[1], v[2], v[3]);
                    *(float4*)(o + 4)  = make_float4(v[4], v[5], v[6], v[7]);
                    *(float4*)(o + 8)  = make_float4(v[8], v[9], v[10], v[11]);
                    *(float4*)(o + 12) = make_float4(v[12], v[13], v[14], v[15]);
                } else if (j < 64) {
                    uint4 u0, u1;
                    uint32_t* uu[8] = {&u0.x, &u0.y, &u0.z, &u0.w, &u1.x, &u1.y, &u1.z, &u1.w};
#pragma unroll
                    for (int p2 = 0; p2 < 8; p2++) {
                        __nv_bfloat16 a = __float2bfloat16_rn(__uint_as_float(r[p2 * 2]));
                        __nv_bfloat16 b = __float2bfloat16_rn(__uint_as_float(r[p2 * 2 + 1]));
                        *uu[p2] = (uint32_t)__bfloat16_as_ushort(a) |
                                  ((uint32_t)__bfloat16_as_ushort(b) << 16);
                    }
                    __nv_bfloat16* o = &g_t2l[(size_t)row * 64 + j];
                    *(uint4*)(o + 0) = u0;
                    *(uint4*)(o + 8) = u1;
                } else {
                    float* o = &g_t2r[(size_t)row * 64 + (j - 64)];
                    *(float4*)(o + 0)  = make_float4(__uint_as_float(r[0]),  __uint_as_float(r[1]),
                                                     __uint_as_float(r[2]),  __uint_as_float(r[3]));
                    *(float4*)(o + 4)  = make_float4(__uint_as_float(r[4]),  __uint_as_float(r[5]),
                                                     __uint_as_float(r[6]),  __uint_as_float(r[7]));
                    *(float4*)(o + 8)  = make_float4(__uint_as_float(r[8]),  __uint_as_float(r[9]),
                                                     __uint_as_float(r[10]), __uint_as_float(r[11]));
                    *(float4*)(o + 12) = make_float4(__uint_as_float(r[12]), __uint_as_float(r[13]),
                                                     __uint_as_float(r[14]), __uint_as_float(r[15]));
                }
            }
        }
    }
    __syncthreads();
    if (t == 0) {
        asm volatile("mbarrier.inval.shared.b64 [%0];" :: "r"(sb + SM_MBAR) : "memory");
    }
    if (wid == 0) TCGEN05_DEALLOC(tmem, 128);

#else  // ---------------- SIMT f32x2 fallback (base-arch compilation) ----------------
    float* As = (float*)smem;               // [128][16]
    float* Ws = (float*)(smem + 8192);      // [16][128]
    int tx = t & 15;
    int ty = t >> 4;

    unsigned long long acc[8][4];
#pragma unroll
    for (int r = 0; r < 8; r++)
#pragma unroll
        for (int c = 0; c < 4; c++) acc[r][c] = 0ull;

#pragma unroll 1
    for (int ph = 0; ph < nPhases; ph++) {
        const float* A = (layer == 1) ? (ph == 0 ? g_mean1 : x) : g_h;
#pragma unroll 1
        for (int kc = 0; kc < 128; kc += 16) {
            __syncthreads();
#pragma unroll
            for (int i = 0; i < 2; i++) {
                int idx = t + i * 256;
                int row = idx >> 2;
                int k4 = (idx & 3) << 2;
                int gr = rowBase + row;
                float4 v = make_float4(0.f, 0.f, 0.f, 0.f);
                if (gr < N_NODES) v = *(const float4*)&A[(size_t)gr * 128 + kc + k4];
                *(float4*)&As[row * 16 + k4] = v;
            }
#pragma unroll
            for (int i = 0; i < 2; i++) {
                int idx = t + i * 256;
                int k = idx >> 5;
                int j4 = (idx & 31) << 2;
                float4 v;
                if (layer == 1) {
                    const float* W = (ph == 0) ? W1l : W1r;
                    v = *(const float4*)&W[(kc + k) * 128 + j4];
                } else {
                    if (j4 < 64) v = *(const float4*)&W2l[(kc + k) * 64 + j4];
                    else         v = *(const float4*)&W2r[(kc + k) * 64 + (j4 - 64)];
                }
                *(float4*)&Ws[k * 128 + j4] = v;
            }
            __syncthreads();
#pragma unroll
            for (int k = 0; k < 16; k++) {
                float4 blo = *(const float4*)&Ws[k * 128 + tx * 8];
                float4 bhi = *(const float4*)&Ws[k * 128 + tx * 8 + 4];
                unsigned long long bp0 = pk2(blo.x, blo.y);
                unsigned long long bp1 = pk2(blo.z, blo.w);
                unsigned long long bp2 = pk2(bhi.x, bhi.y);
                unsigned long long bp3 = pk2(bhi.z, bhi.w);
#pragma unroll
                for (int r = 0; r < 8; r++) {
                    float a = As[(ty * 8 + r) * 16 + k];
                    unsigned long long a2 = pk2(a, a);
                    acc[r][0] = ffma2(a2, bp0, acc[r][0]);
                    acc[r][1] = ffma2(a2, bp1, acc[r][1]);
                    acc[r][2] = ffma2(a2, bp2, acc[r][2]);
                    acc[r][3] = ffma2(a2, bp3, acc[r][3]);
                }
            }
        }
    }
#pragma unroll
    for (int r = 0; r < 8; r++) {
        int row = rowBase + ty * 8 + r;
        if (row < N_NODES) {
#pragma unroll
            for (int c = 0; c < 4; c++) {
                float f0, f1;
                upk2(acc[r][c], f0, f1);
                int j = tx * 8 + c * 2;
                if (layer == 1) {
                    f0 = fmaxf(f0 + b1[j], 0.f);
                    f1 = fmaxf(f1 + b1[j + 1], 0.f);
                    *(float2*)&g_h[(size_t)row * 128 + j] = make_float2(f0, f1);
                } else if (j < 64) {
                    uint32_t u = (uint32_t)__bfloat16_as_ushort(__float2bfloat16_rn(f0)) |
                                 ((uint32_t)__bfloat16_as_ushort(__float2bfloat16_rn(f1)) << 16);
                    *(uint32_t*)&g_t2l[(size_t)row * 64 + j] = u;
                } else {
                    *(float2*)&g_t2r[(size_t)row * 64 + (j - 64)] = make_float2(f0, f1);
                }
            }
        }
    }
#endif // TC_OK
}

// ---------------- aggregation 2 + epilogue, 8-deep MLP ----------------
// z = relu(segment_mean(t2l) + t2r[self] + b2)
__global__ void agg2_kernel(const float* __restrict__ b2, float* __restrict__ out) {
    int gw = (blockIdx.x * blockDim.x + threadIdx.x) >> 5;
    if (gw >= N_NODES) return;
    int lane = threadIdx.x & 31;
    int col = lane * 2;
    int beg = g_off[gw], end = g_off[gw + 1];
    float2 acc = make_float2(0.f, 0.f);
    int e = beg;
    for (; e + 7 < end; e += 8) {
        uint32_t u[8];
#pragma unroll
        for (int q = 0; q < 8; q++)
            u[q] = *(const uint32_t*)&g_t2l[(size_t)g_csr[e + q] * 64 + col];
        float2 s0 = make_float2(0.f, 0.f), s1 = make_float2(0.f, 0.f);
#pragma unroll
        for (int q = 0; q < 8; q += 2) {
            float2 f0 = __bfloat1622float2(*(__nv_bfloat162*)&u[q]);
            float2 f1 = __bfloat1622float2(*(__nv_bfloat162*)&u[q + 1]);
            s0.x += f0.x; s0.y += f0.y;
            s1.x += f1.x; s1.y += f1.y;
        }
        acc.x += s0.x + s1.x;
        acc.y += s0.y + s1.y;
    }
    for (; e < end; e++) {
        uint32_t u = *(const uint32_t*)&g_t2l[(size_t)g_csr[e] * 64 + col];
        float2 f = __bfloat1622float2(*(__nv_bfloat162*)&u);
        acc.x += f.x; acc.y += f.y;
    }
    int deg = end - beg;
    float inv = 1.f / (float)(deg > 1 ? deg : 1);
    float2 rr = *(const float2*)&g_t2r[(size_t)gw * 64 + col];
    float o0 = fmaxf(acc.x * inv + rr.x + b2[col], 0.f);
    float o1 = fmaxf(acc.y * inv + rr.y + b2[col + 1], 0.f);
    *(float2*)&out[(size_t)gw * 64 + col] = make_float2(o0, o1);
}

// ---------------- launch ----------------
extern "C" void kernel_launch(void* const* d_in, const int* in_sizes, int n_in,
                              void* d_out, int out_size) {
    const float* x   = (const float*)d_in[0];
    const int*   ei  = (const int*)d_in[1];
    const float* W1l = (const float*)d_in[2];
    const float* W1r = (const float*)d_in[3];
    const float* b1  = (const float*)d_in[4];
    const float* W2l = (const float*)d_in[5];
    const float* W2r = (const float*)d_in[6];
    const float* b2  = (const float*)d_in[7];
    float* out = (float*)d_out;

    (void)in_sizes; (void)n_in; (void)out_size;

    cudaFuncSetAttribute(gemm_tc_kernel, cudaFuncAttributeMaxDynamicSharedMemorySize,
                         GEMM_SMEM);

    const int NB_SCAN = (N_NODES + 1023) / 1024;       // 98
    const int EB      = (N_EDGES + 255) / 256;         // 6250
    const int GEMMB   = (N_NODES + 127) / 128;         // 782
    const int AGGB    = (N_NODES + 7) / 8;             // 12500

    init_pack_kernel<<<(N_NODES + 255) / 256, 256>>>(ei, W1l, W1r, W2l, W2r);   // #1
    hist_kernel<<<EB, 256>>>(ei);                                               // #2
    scan1_kernel<<<NB_SCAN, 256>>>();                                           // #3
    scan3m_kernel<<<NB_SCAN, 256>>>();                                          // #4
    build_kernel<<<EB, 256>>>(ei);                                              // #5
    agg1_kernel<<<AGGB, 256>>>(x);                                              // #6
    gemm_tc_kernel<<<GEMMB, 256, GEMM_SMEM>>>(x, W1l, W1r, b1, W2l, W2r, 1);    // #7
    gemm_tc_kernel<<<GEMMB, 256, GEMM_SMEM>>>(x, W1l, W1r, b1, W2l, W2r, 2);    // #8
    agg2_kernel<<<AGGB, 256>>>(b2, out);                                        // #9
}